// round 12
// baseline (speedup 1.0000x reference)
#include <cuda_runtime.h>
#include <cuda_bf16.h>
#include <cstdint>

// SC2_KNN: deformed = pc1 + pred_flow; voxelize into (800,800,45) grid
// (cell 0.1 => multiply by 10.0f, matching XLA's A/const -> A*(1/const)
// rewrite where fp32(1/0.1f) == 10.0f exactly); gather nn_cell from
// full_ids (3 channels), gather nn_idx from orig_index_grid, distance to
// pc2[nn_idx]. Outputs: dist[N] then idx[N] (as float) concatenated.
//
// R12: best config (R10: scalar 4B gathers on generic path + evict_last
// hint, .cs evict-first streams, 128-thread blocks) + 2 points/thread
// with interleaved independent gather chains to double per-warp MLP in
// the now partially-L2-resident steady state. Scalar gathers kept: 4B
// warp-wide gathers are wavefront-minimal (R11 showed v2 regresses).

#define GXD 800
#define GYD 800
#define GZD 45

__device__ __forceinline__ uint64_t evict_last_policy() {
    uint64_t pol;
    asm("createpolicy.fractional.L2::evict_last.b64 %0, 1.0;" : "=l"(pol));
    return pol;
}
__device__ __forceinline__ int ldg_gen_i32(const int* p, uint64_t pol) {
    int v;
    asm("ld.global.L2::cache_hint.s32 %0, [%1], %2;"
        : "=r"(v) : "l"(p), "l"(pol));
    return v;
}
__device__ __forceinline__ float ldg_gen_f32(const float* p, uint64_t pol) {
    float v;
    asm("ld.global.L2::cache_hint.f32 %0, [%1], %2;"
        : "=f"(v) : "l"(p), "l"(pol));
    return v;
}
__device__ __forceinline__ float ldg_stream_f32(const float* p) {
    float v;
    asm("ld.global.cs.nc.f32 %0, [%1];" : "=f"(v) : "l"(p));
    return v;
}
__device__ __forceinline__ void stg_stream_f32(float* p, float v) {
    asm volatile("st.global.cs.f32 [%0], %1;" :: "l"(p), "f"(v));
}

__global__ __launch_bounds__(128) void SC2_KNN_kernel(
                               const float* __restrict__ pc1,
                               const float* __restrict__ flow,
                               const float* __restrict__ pc2,
                               const int*   __restrict__ full_ids,
                               const int*   __restrict__ grid,
                               float*       __restrict__ out,
                               int n, int half) {
    int i = blockIdx.x * blockDim.x + threadIdx.x;
    if (i >= half) return;
    int j = i + half;

    uint64_t pol = evict_last_policy();

    // front-batched coalesced streaming loads (12 independent LDGs)
    float a0 = ldg_stream_f32(pc1 + 3 * i + 0), f0 = ldg_stream_f32(flow + 3 * i + 0);
    float a1 = ldg_stream_f32(pc1 + 3 * i + 1), f1 = ldg_stream_f32(flow + 3 * i + 1);
    float a2 = ldg_stream_f32(pc1 + 3 * i + 2), f2 = ldg_stream_f32(flow + 3 * i + 2);
    float b0 = ldg_stream_f32(pc1 + 3 * j + 0), g0 = ldg_stream_f32(flow + 3 * j + 0);
    float b1 = ldg_stream_f32(pc1 + 3 * j + 1), g1 = ldg_stream_f32(flow + 3 * j + 1);
    float b2 = ldg_stream_f32(pc1 + 3 * j + 2), g2 = ldg_stream_f32(flow + 3 * j + 2);

    float dA0 = __fadd_rn(a0, f0), dA1 = __fadd_rn(a1, f1), dA2 = __fadd_rn(a2, f2);
    float dB0 = __fadd_rn(b0, g0), dB1 = __fadd_rn(b1, g1), dB2 = __fadd_rn(b2, g2);

    int axi = (int)__fmul_rn(__fadd_rn(dA0, 40.0f), 10.0f);
    int ayi = (int)__fmul_rn(__fadd_rn(dA1, 40.0f), 10.0f);
    int azi = (int)__fmul_rn(__fadd_rn(dA2,  1.0f), 10.0f);
    int bxi = (int)__fmul_rn(__fadd_rn(dB0, 40.0f), 10.0f);
    int byi = (int)__fmul_rn(__fadd_rn(dB1, 40.0f), 10.0f);
    int bzi = (int)__fmul_rn(__fadd_rn(dB2,  1.0f), 10.0f);
    axi = min(max(axi, 0), GXD - 1);
    ayi = min(max(ayi, 0), GYD - 1);
    azi = min(max(azi, 0), GZD - 1);
    bxi = min(max(bxi, 0), GXD - 1);
    byi = min(max(byi, 0), GYD - 1);
    bzi = min(max(bzi, 0), GZD - 1);

    const int CH = GXD * GYD * GZD;
    int cellA = (axi * GYD + ayi) * GZD + azi;
    int cellB = (bxi * GYD + byi) * GZD + bzi;

    // 6 independent full_ids gathers in flight
    int cA0 = ldg_gen_i32(full_ids + cellA,          pol);
    int cB0 = ldg_gen_i32(full_ids + cellB,          pol);
    int cA1 = ldg_gen_i32(full_ids + CH + cellA,     pol);
    int cB1 = ldg_gen_i32(full_ids + CH + cellB,     pol);
    int cA2 = ldg_gen_i32(full_ids + 2 * CH + cellA, pol);
    int cB2 = ldg_gen_i32(full_ids + 2 * CH + cellB, pol);

    // 2 independent grid gathers
    int nnA = ldg_gen_i32(grid + (cA0 * GYD + cA1) * GZD + cA2, pol);
    int nnB = ldg_gen_i32(grid + (cB0 * GYD + cB1) * GZD + cB2, pol);

    // 6 independent scalar pc2 gathers (wavefront-minimal)
    float pA0 = ldg_gen_f32(pc2 + 3 * nnA + 0, pol);
    float pB0 = ldg_gen_f32(pc2 + 3 * nnB + 0, pol);
    float pA1 = ldg_gen_f32(pc2 + 3 * nnA + 1, pol);
    float pB1 = ldg_gen_f32(pc2 + 3 * nnB + 1, pol);
    float pA2 = ldg_gen_f32(pc2 + 3 * nnA + 2, pol);
    float pB2 = ldg_gen_f32(pc2 + 3 * nnB + 2, pol);

    float xA = pA0 - dA0, yA = pA1 - dA1, zA = pA2 - dA2;
    float xB = pB0 - dB0, yB = pB1 - dB1, zB = pB2 - dB2;
    float distA = sqrtf(xA * xA + yA * yA + zA * zA);
    float distB = sqrtf(xB * xB + yB * yB + zB * zB);

    stg_stream_f32(out + i,     distA);
    stg_stream_f32(out + j,     distB);
    stg_stream_f32(out + n + i, (float)nnA);
    stg_stream_f32(out + n + j, (float)nnB);
}

extern "C" void kernel_launch(void* const* d_in, const int* in_sizes, int n_in,
                              void* d_out, int out_size) {
    const float* pc1      = (const float*)d_in[0];
    const float* flow     = (const float*)d_in[1];
    const float* pc2      = (const float*)d_in[2];
    const int*   full_ids = (const int*)d_in[3];
    const int*   grid     = (const int*)d_in[4];
    float*       out      = (float*)d_out;

    int n = in_sizes[0] / 3;           // pc1 has (1, N, 3) -> 3N elements
    int half = n / 2;                  // N = 200000, even
    int threads = 128;
    int blocks  = (half + threads - 1) / threads;
    SC2_KNN_kernel<<<blocks, threads>>>(pc1, flow, pc2, full_ids, grid, out, n, half);
}

// round 13
// speedup vs baseline: 1.1800x; 1.1800x over previous
#include <cuda_runtime.h>
#include <cuda_bf16.h>
#include <cstdint>

// SC2_KNN: deformed = pc1 + pred_flow; voxelize into (800,800,45) grid
// (cell 0.1 => multiply by 10.0f, matching XLA's A/const -> A*(1/const)
// rewrite where fp32(1/0.1f) == 10.0f exactly); gather nn_cell from
// full_ids (3 channels), gather nn_idx from orig_index_grid, distance to
// pc2[nn_idx]. Outputs: dist[N] then idx[N] (as float) concatenated.
//
// R13: L1 partitioning by access pattern. full_ids/grid gathers (~100 MB
// set, 0% L1 hit) now bypass L1 via __ldcg (L2-only) so they stop
// evicting pc2, whose per-SM distinct-line set (~220 KB) fits L1 and has
// ~2.3x reuse. pc2 uses default .ca loads. Streams keep the R5-winning
// .cs evict-first demotion (__ldcs/__stcs). 1 pt/thread (R12 showed
// 2pt/thread regresses warm), 128-thread blocks (R10).

#define GXD 800
#define GYD 800
#define GZD 45

__global__ __launch_bounds__(128) void SC2_KNN_kernel(
                               const float* __restrict__ pc1,
                               const float* __restrict__ flow,
                               const float* __restrict__ pc2,
                               const int*   __restrict__ full_ids,
                               const int*   __restrict__ grid,
                               float*       __restrict__ out,
                               int n) {
    int i = blockIdx.x * blockDim.x + threadIdx.x;
    if (i >= n) return;

    // coalesced streaming point loads (evict-first: no cache churn)
    float d0 = __fadd_rn(__ldcs(pc1 + 3 * i + 0), __ldcs(flow + 3 * i + 0));
    float d1 = __fadd_rn(__ldcs(pc1 + 3 * i + 1), __ldcs(flow + 3 * i + 1));
    float d2 = __fadd_rn(__ldcs(pc1 + 3 * i + 2), __ldcs(flow + 3 * i + 2));

    // voxelize: (d - min_range) * 10.0f, truncate, clip.
    int gx = (int)__fmul_rn(__fadd_rn(d0, 40.0f), 10.0f);
    int gy = (int)__fmul_rn(__fadd_rn(d1, 40.0f), 10.0f);
    int gz = (int)__fmul_rn(__fadd_rn(d2,  1.0f), 10.0f);
    gx = min(max(gx, 0), GXD - 1);
    gy = min(max(gy, 0), GYD - 1);
    gz = min(max(gz, 0), GZD - 1);

    // full_ids: shape (3, GX, GY, GZ). channel stride = 28,800,000 (< 2^31)
    // L2-only (__ldcg): zero L1 reuse, don't churn L1.
    const int CH = GXD * GYD * GZD;
    int cell = (gx * GYD + gy) * GZD + gz;
    int c0 = __ldcg(full_ids + cell);
    int c1 = __ldcg(full_ids + CH + cell);
    int c2 = __ldcg(full_ids + 2 * CH + cell);

    // orig_index_grid: shape (GX, GY, GZ) — L2-only as well.
    int nn = __ldcg(grid + (c0 * GYD + c1) * GZD + c2);

    // pc2[3*nn..3*nn+2]: default .ca — the ONLY L1-resident array now;
    // per-SM distinct lines (~220 KB) fit L1 with ~2.3x reuse.
    float x = pc2[3 * nn + 0] - d0;
    float y = pc2[3 * nn + 1] - d1;
    float z = pc2[3 * nn + 2] - d2;
    float dist = sqrtf(x * x + y * y + z * z);

    __stcs(out + i,     dist);
    __stcs(out + n + i, (float)nn);
}

extern "C" void kernel_launch(void* const* d_in, const int* in_sizes, int n_in,
                              void* d_out, int out_size) {
    const float* pc1      = (const float*)d_in[0];
    const float* flow     = (const float*)d_in[1];
    const float* pc2      = (const float*)d_in[2];
    const int*   full_ids = (const int*)d_in[3];
    const int*   grid     = (const int*)d_in[4];
    float*       out      = (float*)d_out;

    int n = in_sizes[0] / 3;           // pc1 has (1, N, 3) -> 3N elements
    int threads = 128;
    int blocks  = (n + threads - 1) / threads;
    SC2_KNN_kernel<<<blocks, threads>>>(pc1, flow, pc2, full_ids, grid, out, n);
}